// round 15
// baseline (speedup 1.0000x reference)
#include <cuda_runtime.h>
#include <cuda_fp16.h>
#include <cstdint>

#define NNODES    50000
#define NROWS_PAD 50048
#define NEDGES    100000
#define DIM       768
#define NOUT      1536       // T cols: [x@Wl^T (768) | x@Wr^T (768)]

// ---- scratch (allocation-free rule: __device__ globals) -------------------
__device__ __half g_T[(size_t)NROWS_PAD * NOUT];            // 154 MB (fp16)
__device__ __half g_A[(size_t)NROWS_PAD * DIM];             // 77 MB (fp16)
__device__ __half g_W1[(size_t)NOUT * DIM];                 // 2.4 MB
__device__ __half g_W2[(size_t)NOUT * DIM];                 // 2.4 MB
__device__ int    g_cnt[NNODES];
__device__ int    g_off[NNODES + 1];
__device__ int    g_cur[NNODES];
__device__ int    g_csr_src[NEDGES];

// ---------------------------------------------------------------------------
__device__ __forceinline__ uint32_t smem_u32(const void* p) {
    uint32_t a;
    asm("{ .reg .u64 t; cvta.to.shared.u64 t, %1; cvt.u32.u64 %0, t; }"
        : "=r"(a) : "l"(p));
    return a;
}

// ---------------------------------------------------------------------------
// CSR build
// ---------------------------------------------------------------------------
__global__ void count_deg(const int* __restrict__ ei, int* __restrict__ cnt) {
    int e = blockIdx.x * blockDim.x + threadIdx.x;
    if (e < NEDGES) atomicAdd(&cnt[ei[NEDGES + e]], 1);
}
// single-block exclusive scan, shuffle-based
__global__ void __launch_bounds__(1024) exscan(
    const int* __restrict__ cnt, int* __restrict__ off, int* __restrict__ cur)
{
    __shared__ int wsum[32];
    __shared__ int s_carry;
    const int lane = threadIdx.x & 31;
    const int w    = threadIdx.x >> 5;
    if (threadIdx.x == 0) s_carry = 0;
    __syncthreads();

    for (int base = 0; base < NNODES; base += 1024) {
        int i = base + threadIdx.x;
        int orig = (i < NNODES) ? cnt[i] : 0;
        int v = orig;
#pragma unroll
        for (int o = 1; o < 32; o <<= 1) {
            int t = __shfl_up_sync(0xFFFFFFFFu, v, o);
            if (lane >= o) v += t;
        }
        if (lane == 31) wsum[w] = v;
        __syncthreads();
        if (w == 0) {
            int ws = wsum[lane];
#pragma unroll
            for (int o = 1; o < 32; o <<= 1) {
                int t = __shfl_up_sync(0xFFFFFFFFu, ws, o);
                if (lane >= o) ws += t;
            }
            wsum[lane] = ws;
        }
        __syncthreads();
        int wpre = (w == 0) ? 0 : wsum[w - 1];
        int excl = v - orig + wpre + s_carry;
        if (i < NNODES) { off[i] = excl; cur[i] = excl; }
        __syncthreads();
        if (threadIdx.x == 0) s_carry += wsum[31];
        __syncthreads();
    }
    if (threadIdx.x == 0) off[NNODES] = s_carry;
}
__global__ void fill_csr(const int* __restrict__ ei, int* __restrict__ cur,
                         int* __restrict__ csr_src)
{
    int e = blockIdx.x * blockDim.x + threadIdx.x;
    if (e < NEDGES) {
        int pos = atomicAdd(&cur[ei[NEDGES + e]], 1);
        csr_src[pos] = ei[e];
    }
}

// ---------------------------------------------------------------------------
// fp16 conversion prep kernels
// ---------------------------------------------------------------------------
__global__ void convert_x(const float4* __restrict__ x, __half* __restrict__ A) {
    const int F4 = DIM / 4;
    int i = blockIdx.x * blockDim.x + threadIdx.x;
    if (i >= NROWS_PAD * F4) return;
    int r = i / F4;
    float4 v = make_float4(0.f, 0.f, 0.f, 0.f);
    if (r < NNODES) v = x[i];
    __half2* dst = (__half2*)(A + (size_t)i * 4);
    dst[0] = __floats2half2_rn(v.x, v.y);
    dst[1] = __floats2half2_rn(v.z, v.w);
}
__global__ void convert_w2(const float4* __restrict__ W1l, const float4* __restrict__ W1r,
                           const float4* __restrict__ W2l, const float4* __restrict__ W2r,
                           __half* __restrict__ W1, __half* __restrict__ W2)
{
    const int F4 = DIM / 4;
    int i = blockIdx.x * blockDim.x + threadIdx.x;
    if (i >= NOUT * F4) return;
    float4 v1 = (i < DIM * F4) ? W1l[i] : W1r[i - DIM * F4];
    float4 v2 = (i < DIM * F4) ? W2l[i] : W2r[i - DIM * F4];
    __half2* d1 = (__half2*)(W1 + (size_t)i * 4);
    __half2* d2 = (__half2*)(W2 + (size_t)i * 4);
    d1[0] = __floats2half2_rn(v1.x, v1.y);
    d1[1] = __floats2half2_rn(v1.z, v1.w);
    d2[0] = __floats2half2_rn(v2.x, v2.y);
    d2[1] = __floats2half2_rn(v2.z, v2.w);
}

// ---------------------------------------------------------------------------
// Fused CSR aggregation + normalize + bias + residual on fp16 T.  v2:
// 2 nodes per 192-thread block (independent 96-lane groups), uint4 (8-half)
// loads, residual+bias hoisted above the edge loop, 2-way edge unroll.
// Layer 1: relu + fp16 store into A.  Layer 2: fp32 store into out.
// ---------------------------------------------------------------------------
__device__ __forceinline__ void h8_to_f8(uint4 raw, float* f) {
    float2 p0 = __half22float2(*(__half2*)&raw.x);
    float2 p1 = __half22float2(*(__half2*)&raw.y);
    float2 p2 = __half22float2(*(__half2*)&raw.z);
    float2 p3 = __half22float2(*(__half2*)&raw.w);
    f[0] = p0.x; f[1] = p0.y; f[2] = p1.x; f[3] = p1.y;
    f[4] = p2.x; f[5] = p2.y; f[6] = p3.x; f[7] = p3.y;
}

__global__ void __launch_bounds__(192) agg_combine(
    const __half* __restrict__ T, const int* __restrict__ off,
    const int* __restrict__ csr_src, const float* __restrict__ bias,
    __half* __restrict__ dstH, float* __restrict__ dstF)
{
    const int grp = threadIdx.x / 96;                 // 0/1: node within block
    const int l   = threadIdx.x % 96;                 // 96 lanes x 8 halves = 768
    const int d   = blockIdx.x * 2 + grp;
    const int c8  = l * 8;
    const int beg = off[d], end = off[d + 1];

    // hoisted independent loads: residual + bias (overlap edge-gather latency)
    uint4 traw = *(const uint4*)(T + (size_t)d * NOUT + DIM + c8);
    float4 b0 = *(const float4*)(bias + c8);
    float4 b1 = *(const float4*)(bias + c8 + 4);

    float acc[8] = {0.f, 0.f, 0.f, 0.f, 0.f, 0.f, 0.f, 0.f};
    int i = beg;
    for (; i + 1 < end; i += 2) {
        int s0 = csr_src[i], s1 = csr_src[i + 1];
        uint4 r0 = *(const uint4*)(T + (size_t)s0 * NOUT + c8);
        uint4 r1 = *(const uint4*)(T + (size_t)s1 * NOUT + c8);
        float f0[8], f1[8];
        h8_to_f8(r0, f0); h8_to_f8(r1, f1);
#pragma unroll
        for (int k = 0; k < 8; ++k) acc[k] += f0[k] + f1[k];
    }
    if (i < end) {
        int s = csr_src[i];
        uint4 r = *(const uint4*)(T + (size_t)s * NOUT + c8);
        float f[8];
        h8_to_f8(r, f);
#pragma unroll
        for (int k = 0; k < 8; ++k) acc[k] += f[k];
    }

    float inv = 1.0f / (float)max(end - beg, 1);
    float t[8];
    h8_to_f8(traw, t);
    float b[8] = {b0.x, b0.y, b0.z, b0.w, b1.x, b1.y, b1.z, b1.w};
    float v[8];
#pragma unroll
    for (int k = 0; k < 8; ++k) v[k] = acc[k] * inv + b[k] + t[k];

    if (dstH) {
        uint4 o;
        *(__half2*)&o.x = __floats2half2_rn(fmaxf(v[0], 0.f), fmaxf(v[1], 0.f));
        *(__half2*)&o.y = __floats2half2_rn(fmaxf(v[2], 0.f), fmaxf(v[3], 0.f));
        *(__half2*)&o.z = __floats2half2_rn(fmaxf(v[4], 0.f), fmaxf(v[5], 0.f));
        *(__half2*)&o.w = __floats2half2_rn(fmaxf(v[6], 0.f), fmaxf(v[7], 0.f));
        *(uint4*)(dstH + (size_t)d * DIM + c8) = o;
    } else {
        float* orow = dstF + (size_t)d * DIM + c8;
        *(float4*)(orow + 0) = make_float4(v[0], v[1], v[2], v[3]);
        *(float4*)(orow + 4) = make_float4(v[4], v[5], v[6], v[7]);
    }
}

// ---------------------------------------------------------------------------
// fp16 mma.sync GEMM: T[128m x 128n] = A @ W^T (K=768), fp16 output.
// BM=128 BN=128 BK=64 halves (128B rows), 256 threads / 8 warps (2m x 4n),
// warp tile 64x32, m16n8k16 f16.f32, 3-slot cp.async pipeline, 2 CTAs/SM.
// (unchanged from R13 — at ~94% of HMMA issue floor)
// ---------------------------------------------------------------------------
#define BM 128
#define BN 128
#define ROW_B 128
#define ATILE_B (BM * ROW_B)        // 16 KB
#define BTILE_B (BN * ROW_B)        // 16 KB
#define STG_B   (ATILE_B + BTILE_B) // 32 KB
#define NSLOT 3
#define SMEM_GEMM (NSLOT * STG_B)   // 96 KB
#define NCH 12                      // 768 / 64 halves
#define AROW_BYTES (DIM * 2)        // 1536

__device__ __forceinline__ void cp_async16(uint32_t saddr, const void* gaddr) {
    asm volatile("cp.async.cg.shared.global [%0], [%1], 16;"
                 :: "r"(saddr), "l"(gaddr));
}
__device__ __forceinline__ void cp_commit() {
    asm volatile("cp.async.commit_group;" ::: "memory");
}
__device__ __forceinline__ void cp_wait1() {
    asm volatile("cp.async.wait_group 1;" ::: "memory");
}
__device__ __forceinline__ void ldmatrix4(uint32_t* a, uint32_t addr) {
    asm volatile("ldmatrix.sync.aligned.m8n8.x4.shared.b16 {%0,%1,%2,%3}, [%4];"
                 : "=r"(a[0]), "=r"(a[1]), "=r"(a[2]), "=r"(a[3]) : "r"(addr));
}
__device__ __forceinline__ void mma_fp16(float* c, const uint32_t* a, const uint32_t* b) {
    asm volatile(
        "mma.sync.aligned.m16n8k16.row.col.f32.f16.f16.f32 "
        "{%0,%1,%2,%3}, {%4,%5,%6,%7}, {%8,%9}, {%0,%1,%2,%3};"
        : "+f"(c[0]), "+f"(c[1]), "+f"(c[2]), "+f"(c[3])
        : "r"(a[0]), "r"(a[1]), "r"(a[2]), "r"(a[3]), "r"(b[0]), "r"(b[1]));
}

// 256 threads: 8 cp.async each (4 A rows, 4 B rows)
__device__ __forceinline__ void load_stage(
    uint32_t slot_base, const char* Ab, const char* Bb, size_t goff, int tid)
{
    const int j  = tid & 7;        // 16B chunk in 128B row
    const int r0 = tid >> 3;       // 0..31
    const size_t gj = goff + (size_t)j * 16;
#pragma unroll
    for (int s = 0; s < 4; ++s) {
        int row = r0 + s * 32;
        uint32_t soff = row * ROW_B + ((j ^ (row & 7)) << 4);
        cp_async16(slot_base + soff, Ab + (size_t)row * AROW_BYTES + gj);
        cp_async16(slot_base + ATILE_B + soff, Bb + (size_t)row * AROW_BYTES + gj);
    }
}

__global__ void __launch_bounds__(256, 2) gemm_fp16(
    const __half* __restrict__ A, const __half* __restrict__ W,
    __half* __restrict__ T)
{
    extern __shared__ char smem[];
    const uint32_t sb = smem_u32(smem);
    const int tid = threadIdx.x;
    const int wid = tid >> 5, lid = tid & 31;
    const int wm = (wid & 1) * 64;        // 2 m-warps
    const int wn = (wid >> 1) * 32;       // 4 n-warps
    const int n0 = blockIdx.x * BN;
    const int m0 = blockIdx.y * BM;

    const char* Ab = (const char*)A + (size_t)m0 * AROW_BYTES;
    const char* Bb = (const char*)W + (size_t)n0 * AROW_BYTES;

    float acc[4][4][4];                   // 64 accumulators
#pragma unroll
    for (int i = 0; i < 4; i++)
#pragma unroll
        for (int j = 0; j < 4; j++)
#pragma unroll
            for (int k = 0; k < 4; k++) acc[i][j][k] = 0.f;

#pragma unroll
    for (int p = 0; p < 2; ++p) {
        load_stage(sb + p * STG_B, Ab, Bb, (size_t)p * 128, tid);
        cp_commit();
    }

    uint32_t rowoffA[4], swzA[4];
    const uint32_t hiA = lid >> 4;
#pragma unroll
    for (int mt = 0; mt < 4; ++mt) {
        int r = wm + mt * 16 + (lid & 7) + ((lid >> 3) & 1) * 8;
        rowoffA[mt] = r * ROW_B;
        swzA[mt] = r & 7;
    }
    uint32_t rowoffB[2], swzB[2];
    const uint32_t hiB = (lid >> 3) & 1;
#pragma unroll
    for (int bt = 0; bt < 2; ++bt) {
        int r = wn + bt * 16 + (lid & 7) + (lid >> 4) * 8;
        rowoffB[bt] = ATILE_B + r * ROW_B;
        swzB[bt] = r & 7;
    }

    int slot = 0;
    for (int c = 0; c < NCH; ++c) {
        cp_wait1();
        __syncthreads();   // stage c ready; all warps done reading stage c-1

        const int cn = c + 2;
        const int wslot = (slot + 2 >= NSLOT) ? slot + 2 - NSLOT : slot + 2;
        if (cn < NCH) load_stage(sb + wslot * STG_B, Ab, Bb,
                                 (size_t)cn * 128, tid);
        cp_commit();

        const uint32_t sS = sb + slot * STG_B;
#pragma unroll
        for (int ks = 0; ks < 4; ++ks) {      // 4 x k16 per 64-half chunk
            uint32_t bfrag[4][2];
#pragma unroll
            for (int bt = 0; bt < 2; ++bt) {
                uint32_t r[4];
                ldmatrix4(r, sS + rowoffB[bt] +
                             (((ks * 2 + hiB) ^ swzB[bt]) << 4));
                bfrag[bt * 2 + 0][0] = r[0]; bfrag[bt * 2 + 0][1] = r[1];
                bfrag[bt * 2 + 1][0] = r[2]; bfrag[bt * 2 + 1][1] = r[3];
            }
#pragma unroll
            for (int mt = 0; mt < 4; ++mt) {
                uint32_t afrag[4];
                ldmatrix4(afrag, sS + rowoffA[mt] +
                                 (((ks * 2 + hiA) ^ swzA[mt]) << 4));
#pragma unroll
                for (int nt = 0; nt < 4; ++nt)
                    mma_fp16(acc[mt][nt], afrag, bfrag[nt]);
            }
        }
        slot = (slot + 1 == NSLOT) ? 0 : slot + 1;
    }

    // epilogue: fp16 store to T
#pragma unroll
    for (int mt = 0; mt < 4; ++mt) {
        int row_lo = m0 + wm + mt * 16 + (lid >> 2);
#pragma unroll
        for (int h = 0; h < 2; ++h) {
            int row = row_lo + h * 8;
            __half* orow = T + (size_t)row * NOUT;
#pragma unroll
            for (int nt = 0; nt < 4; ++nt) {
                int col = n0 + wn + nt * 8 + (lid & 3) * 2;
                *(__half2*)(orow + col) =
                    __floats2half2_rn(acc[mt][nt][h * 2 + 0],
                                      acc[mt][nt][h * 2 + 1]);
            }
        }
    }
}

// ---------------------------------------------------------------------------
extern "C" void kernel_launch(void* const* d_in, const int* in_sizes, int n_in,
                              void* d_out, int out_size)
{
    const float* x   = (const float*)d_in[0];
    const int*   ei  = (const int*)d_in[1];     // int32 (JAX x64 disabled)
    const float* W1l = (const float*)d_in[2];
    const float* b1l = (const float*)d_in[3];
    const float* W1r = (const float*)d_in[4];
    const float* W2l = (const float*)d_in[5];
    const float* b2l = (const float*)d_in[6];
    const float* W2r = (const float*)d_in[7];
    float*       out = (float*)d_out;

    __half *T, *A, *W1, *W2;
    int *cnt, *off, *cur, *csr;
    cudaGetSymbolAddress((void**)&T,   g_T);
    cudaGetSymbolAddress((void**)&A,   g_A);
    cudaGetSymbolAddress((void**)&W1,  g_W1);
    cudaGetSymbolAddress((void**)&W2,  g_W2);
    cudaGetSymbolAddress((void**)&cnt, g_cnt);
    cudaGetSymbolAddress((void**)&off, g_off);
    cudaGetSymbolAddress((void**)&cur, g_cur);
    cudaGetSymbolAddress((void**)&csr, g_csr_src);

    cudaFuncSetAttribute(gemm_fp16, cudaFuncAttributeMaxDynamicSharedMemorySize,
                         SMEM_GEMM);

    const int rows_blocks = (NROWS_PAD * (DIM / 4) + 255) / 256;
    const int w_blocks    = (NOUT * (DIM / 4) + 255) / 256;
    const int eb          = (NEDGES + 255) / 256;
    dim3 gg(NOUT / BN, NROWS_PAD / BM);   // (12, 391)

    // ---- Prep ----
    cudaMemsetAsync(cnt, 0, NNODES * sizeof(int));                              // memset node
    convert_x<<<rows_blocks, 256>>>((const float4*)x, A);                       // 1
    convert_w2<<<w_blocks, 256>>>((const float4*)W1l, (const float4*)W1r,
                                  (const float4*)W2l, (const float4*)W2r,
                                  W1, W2);                                      // 2
    count_deg<<<eb, 256>>>(ei, cnt);                                            // 3
    exscan<<<1, 1024>>>(cnt, off, cur);                                         // 4
    fill_csr<<<eb, 256>>>(ei, cur, csr);                                        // 5

    // ---- Layer 1 ----
    gemm_fp16<<<gg, 256, SMEM_GEMM>>>(A, W1, T);                                // 6 (profiled)
    agg_combine<<<NNODES / 2, 192>>>(T, off, csr, b1l, A, nullptr);             // 7

    // ---- Layer 2 ----
    gemm_fp16<<<gg, 256, SMEM_GEMM>>>(A, W2, T);                                // 8
    agg_combine<<<NNODES / 2, 192>>>(T, off, csr, b2l, nullptr, out);           // 9
}

// round 16
// speedup vs baseline: 1.0350x; 1.0350x over previous
#include <cuda_runtime.h>
#include <cuda_fp16.h>
#include <cstdint>

#define NNODES    50000
#define NROWS_PAD 50048
#define NEDGES    100000
#define DIM       768
#define NOUT      1536       // T cols: [x@Wl^T (768) | x@Wr^T (768)]
#define NCHUNKS   49         // ceil(NNODES / 1024)

// ---- scratch (allocation-free rule: __device__ globals) -------------------
__device__ __half g_T[(size_t)NROWS_PAD * NOUT];            // 154 MB (fp16)
__device__ __half g_A[(size_t)NROWS_PAD * DIM];             // 77 MB (fp16)
__device__ __half g_W1[(size_t)NOUT * DIM];                 // 2.4 MB
__device__ __half g_W2[(size_t)NOUT * DIM];                 // 2.4 MB
__device__ int    g_cnt[NNODES];
__device__ int    g_off[NNODES + 1];
__device__ int    g_cur[NNODES];
__device__ int    g_csr_src[NEDGES];
__device__ int    g_bsum[NCHUNKS];
__device__ int    g_bbase[NCHUNKS];

// ---------------------------------------------------------------------------
__device__ __forceinline__ uint32_t smem_u32(const void* p) {
    uint32_t a;
    asm("{ .reg .u64 t; cvta.to.shared.u64 t, %1; cvt.u32.u64 %0, t; }"
        : "=r"(a) : "l"(p));
    return a;
}

// ---------------------------------------------------------------------------
// CSR build — two-level parallel scan
// ---------------------------------------------------------------------------
__global__ void count_deg(const int* __restrict__ ei, int* __restrict__ cnt) {
    int e = blockIdx.x * blockDim.x + threadIdx.x;
    if (e < NEDGES) atomicAdd(&cnt[ei[NEDGES + e]], 1);
}

// level 1a: per-1024-chunk reduction
__global__ void __launch_bounds__(1024) blk_sum(
    const int* __restrict__ cnt, int* __restrict__ bsum)
{
    __shared__ int ws[32];
    int i = blockIdx.x * 1024 + threadIdx.x;
    int v = (i < NNODES) ? cnt[i] : 0;
#pragma unroll
    for (int o = 16; o > 0; o >>= 1) v += __shfl_down_sync(0xFFFFFFFFu, v, o);
    if ((threadIdx.x & 31) == 0) ws[threadIdx.x >> 5] = v;
    __syncthreads();
    if (threadIdx.x < 32) {
        int s = ws[threadIdx.x];
#pragma unroll
        for (int o = 16; o > 0; o >>= 1) s += __shfl_down_sync(0xFFFFFFFFu, s, o);
        if (threadIdx.x == 0) bsum[blockIdx.x] = s;
    }
}

// level 2: scan the 49 chunk sums (single tiny block)
__global__ void __launch_bounds__(64) scan_bsum(
    const int* __restrict__ bsum, int* __restrict__ bbase, int* __restrict__ off)
{
    __shared__ int s[64];
    int v = (threadIdx.x < NCHUNKS) ? bsum[threadIdx.x] : 0;
    s[threadIdx.x] = v;
    __syncthreads();
#pragma unroll
    for (int o = 1; o < 64; o <<= 1) {
        int t = (threadIdx.x >= o) ? s[threadIdx.x - o] : 0;
        __syncthreads();
        s[threadIdx.x] += t;
        __syncthreads();
    }
    if (threadIdx.x < NCHUNKS) bbase[threadIdx.x] = s[threadIdx.x] - v;  // exclusive
    if (threadIdx.x == NCHUNKS - 1) off[NNODES] = s[threadIdx.x];
}

// level 1b: local exclusive scan + chunk base
__global__ void __launch_bounds__(1024) blk_scan(
    const int* __restrict__ cnt, const int* __restrict__ bbase,
    int* __restrict__ off, int* __restrict__ cur)
{
    __shared__ int wsum[32];
    const int lane = threadIdx.x & 31;
    const int w    = threadIdx.x >> 5;
    int i = blockIdx.x * 1024 + threadIdx.x;
    int orig = (i < NNODES) ? cnt[i] : 0;
    int v = orig;
#pragma unroll
    for (int o = 1; o < 32; o <<= 1) {
        int t = __shfl_up_sync(0xFFFFFFFFu, v, o);
        if (lane >= o) v += t;
    }
    if (lane == 31) wsum[w] = v;
    __syncthreads();
    if (w == 0) {
        int ws = wsum[lane];
#pragma unroll
        for (int o = 1; o < 32; o <<= 1) {
            int t = __shfl_up_sync(0xFFFFFFFFu, ws, o);
            if (lane >= o) ws += t;
        }
        wsum[lane] = ws;
    }
    __syncthreads();
    int wpre = (w == 0) ? 0 : wsum[w - 1];
    int excl = v - orig + wpre + bbase[blockIdx.x];
    if (i < NNODES) { off[i] = excl; cur[i] = excl; }
}

__global__ void fill_csr(const int* __restrict__ ei, int* __restrict__ cur,
                         int* __restrict__ csr_src)
{
    int e = blockIdx.x * blockDim.x + threadIdx.x;
    if (e < NEDGES) {
        int pos = atomicAdd(&cur[ei[NEDGES + e]], 1);
        csr_src[pos] = ei[e];
    }
}

// ---------------------------------------------------------------------------
// fp16 conversion prep kernels
// ---------------------------------------------------------------------------
__global__ void convert_x(const float4* __restrict__ x, __half* __restrict__ A) {
    const int F4 = DIM / 4;
    int i = blockIdx.x * blockDim.x + threadIdx.x;
    if (i >= NROWS_PAD * F4) return;
    int r = i / F4;
    float4 v = make_float4(0.f, 0.f, 0.f, 0.f);
    if (r < NNODES) v = x[i];
    __half2* dst = (__half2*)(A + (size_t)i * 4);
    dst[0] = __floats2half2_rn(v.x, v.y);
    dst[1] = __floats2half2_rn(v.z, v.w);
}
__global__ void convert_w2(const float4* __restrict__ W1l, const float4* __restrict__ W1r,
                           const float4* __restrict__ W2l, const float4* __restrict__ W2r,
                           __half* __restrict__ W1, __half* __restrict__ W2)
{
    const int F4 = DIM / 4;
    int i = blockIdx.x * blockDim.x + threadIdx.x;
    if (i >= NOUT * F4) return;
    float4 v1 = (i < DIM * F4) ? W1l[i] : W1r[i - DIM * F4];
    float4 v2 = (i < DIM * F4) ? W2l[i] : W2r[i - DIM * F4];
    __half2* d1 = (__half2*)(W1 + (size_t)i * 4);
    __half2* d2 = (__half2*)(W2 + (size_t)i * 4);
    d1[0] = __floats2half2_rn(v1.x, v1.y);
    d1[1] = __floats2half2_rn(v1.z, v1.w);
    d2[0] = __floats2half2_rn(v2.x, v2.y);
    d2[1] = __floats2half2_rn(v2.z, v2.w);
}

// ---------------------------------------------------------------------------
// Fused CSR aggregation + normalize + bias + residual on fp16 T.
// 2 nodes per 192-thread block, uint4 (8-half) loads, hoisted residual+bias.
// ---------------------------------------------------------------------------
__device__ __forceinline__ void h8_to_f8(uint4 raw, float* f) {
    float2 p0 = __half22float2(*(__half2*)&raw.x);
    float2 p1 = __half22float2(*(__half2*)&raw.y);
    float2 p2 = __half22float2(*(__half2*)&raw.z);
    float2 p3 = __half22float2(*(__half2*)&raw.w);
    f[0] = p0.x; f[1] = p0.y; f[2] = p1.x; f[3] = p1.y;
    f[4] = p2.x; f[5] = p2.y; f[6] = p3.x; f[7] = p3.y;
}

__global__ void __launch_bounds__(192) agg_combine(
    const __half* __restrict__ T, const int* __restrict__ off,
    const int* __restrict__ csr_src, const float* __restrict__ bias,
    __half* __restrict__ dstH, float* __restrict__ dstF)
{
    const int grp = threadIdx.x / 96;                 // 0/1: node within block
    const int l   = threadIdx.x % 96;                 // 96 lanes x 8 halves = 768
    const int d   = blockIdx.x * 2 + grp;
    const int c8  = l * 8;
    const int beg = off[d], end = off[d + 1];

    // hoisted independent loads: residual + bias (overlap edge-gather latency)
    uint4 traw = *(const uint4*)(T + (size_t)d * NOUT + DIM + c8);
    float4 b0 = *(const float4*)(bias + c8);
    float4 b1 = *(const float4*)(bias + c8 + 4);

    float acc[8] = {0.f, 0.f, 0.f, 0.f, 0.f, 0.f, 0.f, 0.f};
    int i = beg;
    for (; i + 1 < end; i += 2) {
        int s0 = csr_src[i], s1 = csr_src[i + 1];
        uint4 r0 = *(const uint4*)(T + (size_t)s0 * NOUT + c8);
        uint4 r1 = *(const uint4*)(T + (size_t)s1 * NOUT + c8);
        float f0[8], f1[8];
        h8_to_f8(r0, f0); h8_to_f8(r1, f1);
#pragma unroll
        for (int k = 0; k < 8; ++k) acc[k] += f0[k] + f1[k];
    }
    if (i < end) {
        int s = csr_src[i];
        uint4 r = *(const uint4*)(T + (size_t)s * NOUT + c8);
        float f[8];
        h8_to_f8(r, f);
#pragma unroll
        for (int k = 0; k < 8; ++k) acc[k] += f[k];
    }

    float inv = 1.0f / (float)max(end - beg, 1);
    float t[8];
    h8_to_f8(traw, t);
    float b[8] = {b0.x, b0.y, b0.z, b0.w, b1.x, b1.y, b1.z, b1.w};
    float v[8];
#pragma unroll
    for (int k = 0; k < 8; ++k) v[k] = acc[k] * inv + b[k] + t[k];

    if (dstH) {
        uint4 o;
        *(__half2*)&o.x = __floats2half2_rn(fmaxf(v[0], 0.f), fmaxf(v[1], 0.f));
        *(__half2*)&o.y = __floats2half2_rn(fmaxf(v[2], 0.f), fmaxf(v[3], 0.f));
        *(__half2*)&o.z = __floats2half2_rn(fmaxf(v[4], 0.f), fmaxf(v[5], 0.f));
        *(__half2*)&o.w = __floats2half2_rn(fmaxf(v[6], 0.f), fmaxf(v[7], 0.f));
        *(uint4*)(dstH + (size_t)d * DIM + c8) = o;
    } else {
        float* orow = dstF + (size_t)d * DIM + c8;
        *(float4*)(orow + 0) = make_float4(v[0], v[1], v[2], v[3]);
        *(float4*)(orow + 4) = make_float4(v[4], v[5], v[6], v[7]);
    }
}

// ---------------------------------------------------------------------------
// fp16 mma.sync GEMM: T[128m x 128n] = A @ W^T (K=768), fp16 output.
// BM=128 BN=128 BK=64 halves, 256 threads / 8 warps (2m x 4n), warp tile
// 64x32, m16n8k16 f16.f32, 3-slot cp.async pipeline, 2 CTAs/SM.
// (unchanged — at ~94% of HMMA issue floor)
// ---------------------------------------------------------------------------
#define BM 128
#define BN 128
#define ROW_B 128
#define ATILE_B (BM * ROW_B)        // 16 KB
#define BTILE_B (BN * ROW_B)        // 16 KB
#define STG_B   (ATILE_B + BTILE_B) // 32 KB
#define NSLOT 3
#define SMEM_GEMM (NSLOT * STG_B)   // 96 KB
#define NCH 12                      // 768 / 64 halves
#define AROW_BYTES (DIM * 2)        // 1536

__device__ __forceinline__ void cp_async16(uint32_t saddr, const void* gaddr) {
    asm volatile("cp.async.cg.shared.global [%0], [%1], 16;"
                 :: "r"(saddr), "l"(gaddr));
}
__device__ __forceinline__ void cp_commit() {
    asm volatile("cp.async.commit_group;" ::: "memory");
}
__device__ __forceinline__ void cp_wait1() {
    asm volatile("cp.async.wait_group 1;" ::: "memory");
}
__device__ __forceinline__ void ldmatrix4(uint32_t* a, uint32_t addr) {
    asm volatile("ldmatrix.sync.aligned.m8n8.x4.shared.b16 {%0,%1,%2,%3}, [%4];"
                 : "=r"(a[0]), "=r"(a[1]), "=r"(a[2]), "=r"(a[3]) : "r"(addr));
}
__device__ __forceinline__ void mma_fp16(float* c, const uint32_t* a, const uint32_t* b) {
    asm volatile(
        "mma.sync.aligned.m16n8k16.row.col.f32.f16.f16.f32 "
        "{%0,%1,%2,%3}, {%4,%5,%6,%7}, {%8,%9}, {%0,%1,%2,%3};"
        : "+f"(c[0]), "+f"(c[1]), "+f"(c[2]), "+f"(c[3])
        : "r"(a[0]), "r"(a[1]), "r"(a[2]), "r"(a[3]), "r"(b[0]), "r"(b[1]));
}

// 256 threads: 8 cp.async each (4 A rows, 4 B rows)
__device__ __forceinline__ void load_stage(
    uint32_t slot_base, const char* Ab, const char* Bb, size_t goff, int tid)
{
    const int j  = tid & 7;        // 16B chunk in 128B row
    const int r0 = tid >> 3;       // 0..31
    const size_t gj = goff + (size_t)j * 16;
#pragma unroll
    for (int s = 0; s < 4; ++s) {
        int row = r0 + s * 32;
        uint32_t soff = row * ROW_B + ((j ^ (row & 7)) << 4);
        cp_async16(slot_base + soff, Ab + (size_t)row * AROW_BYTES + gj);
        cp_async16(slot_base + ATILE_B + soff, Bb + (size_t)row * AROW_BYTES + gj);
    }
}

__global__ void __launch_bounds__(256, 2) gemm_fp16(
    const __half* __restrict__ A, const __half* __restrict__ W,
    __half* __restrict__ T)
{
    extern __shared__ char smem[];
    const uint32_t sb = smem_u32(smem);
    const int tid = threadIdx.x;
    const int wid = tid >> 5, lid = tid & 31;
    const int wm = (wid & 1) * 64;        // 2 m-warps
    const int wn = (wid >> 1) * 32;       // 4 n-warps
    const int n0 = blockIdx.x * BN;
    const int m0 = blockIdx.y * BM;

    const char* Ab = (const char*)A + (size_t)m0 * AROW_BYTES;
    const char* Bb = (const char*)W + (size_t)n0 * AROW_BYTES;

    float acc[4][4][4];                   // 64 accumulators
#pragma unroll
    for (int i = 0; i < 4; i++)
#pragma unroll
        for (int j = 0; j < 4; j++)
#pragma unroll
            for (int k = 0; k < 4; k++) acc[i][j][k] = 0.f;

#pragma unroll
    for (int p = 0; p < 2; ++p) {
        load_stage(sb + p * STG_B, Ab, Bb, (size_t)p * 128, tid);
        cp_commit();
    }

    uint32_t rowoffA[4], swzA[4];
    const uint32_t hiA = lid >> 4;
#pragma unroll
    for (int mt = 0; mt < 4; ++mt) {
        int r = wm + mt * 16 + (lid & 7) + ((lid >> 3) & 1) * 8;
        rowoffA[mt] = r * ROW_B;
        swzA[mt] = r & 7;
    }
    uint32_t rowoffB[2], swzB[2];
    const uint32_t hiB = (lid >> 3) & 1;
#pragma unroll
    for (int bt = 0; bt < 2; ++bt) {
        int r = wn + bt * 16 + (lid & 7) + (lid >> 4) * 8;
        rowoffB[bt] = ATILE_B + r * ROW_B;
        swzB[bt] = r & 7;
    }

    int slot = 0;
    for (int c = 0; c < NCH; ++c) {
        cp_wait1();
        __syncthreads();   // stage c ready; all warps done reading stage c-1

        const int cn = c + 2;
        const int wslot = (slot + 2 >= NSLOT) ? slot + 2 - NSLOT : slot + 2;
        if (cn < NCH) load_stage(sb + wslot * STG_B, Ab, Bb,
                                 (size_t)cn * 128, tid);
        cp_commit();

        const uint32_t sS = sb + slot * STG_B;
#pragma unroll
        for (int ks = 0; ks < 4; ++ks) {      // 4 x k16 per 64-half chunk
            uint32_t bfrag[4][2];
#pragma unroll
            for (int bt = 0; bt < 2; ++bt) {
                uint32_t r[4];
                ldmatrix4(r, sS + rowoffB[bt] +
                             (((ks * 2 + hiB) ^ swzB[bt]) << 4));
                bfrag[bt * 2 + 0][0] = r[0]; bfrag[bt * 2 + 0][1] = r[1];
                bfrag[bt * 2 + 1][0] = r[2]; bfrag[bt * 2 + 1][1] = r[3];
            }
#pragma unroll
            for (int mt = 0; mt < 4; ++mt) {
                uint32_t afrag[4];
                ldmatrix4(afrag, sS + rowoffA[mt] +
                                 (((ks * 2 + hiA) ^ swzA[mt]) << 4));
#pragma unroll
                for (int nt = 0; nt < 4; ++nt)
                    mma_fp16(acc[mt][nt], afrag, bfrag[nt]);
            }
        }
        slot = (slot + 1 == NSLOT) ? 0 : slot + 1;
    }

    // epilogue: fp16 store to T
#pragma unroll
    for (int mt = 0; mt < 4; ++mt) {
        int row_lo = m0 + wm + mt * 16 + (lid >> 2);
#pragma unroll
        for (int h = 0; h < 2; ++h) {
            int row = row_lo + h * 8;
            __half* orow = T + (size_t)row * NOUT;
#pragma unroll
            for (int nt = 0; nt < 4; ++nt) {
                int col = n0 + wn + nt * 8 + (lid & 3) * 2;
                *(__half2*)(orow + col) =
                    __floats2half2_rn(acc[mt][nt][h * 2 + 0],
                                      acc[mt][nt][h * 2 + 1]);
            }
        }
    }
}

// ---------------------------------------------------------------------------
extern "C" void kernel_launch(void* const* d_in, const int* in_sizes, int n_in,
                              void* d_out, int out_size)
{
    const float* x   = (const float*)d_in[0];
    const int*   ei  = (const int*)d_in[1];     // int32 (JAX x64 disabled)
    const float* W1l = (const float*)d_in[2];
    const float* b1l = (const float*)d_in[3];
    const float* W1r = (const float*)d_in[4];
    const float* W2l = (const float*)d_in[5];
    const float* b2l = (const float*)d_in[6];
    const float* W2r = (const float*)d_in[7];
    float*       out = (float*)d_out;

    __half *T, *A, *W1, *W2;
    int *cnt, *off, *cur, *csr, *bsum, *bbase;
    cudaGetSymbolAddress((void**)&T,    g_T);
    cudaGetSymbolAddress((void**)&A,    g_A);
    cudaGetSymbolAddress((void**)&W1,   g_W1);
    cudaGetSymbolAddress((void**)&W2,   g_W2);
    cudaGetSymbolAddress((void**)&cnt,  g_cnt);
    cudaGetSymbolAddress((void**)&off,  g_off);
    cudaGetSymbolAddress((void**)&cur,  g_cur);
    cudaGetSymbolAddress((void**)&csr,  g_csr_src);
    cudaGetSymbolAddress((void**)&bsum, g_bsum);
    cudaGetSymbolAddress((void**)&bbase, g_bbase);

    cudaFuncSetAttribute(gemm_fp16, cudaFuncAttributeMaxDynamicSharedMemorySize,
                         SMEM_GEMM);

    const int rows_blocks = (NROWS_PAD * (DIM / 4) + 255) / 256;
    const int w_blocks    = (NOUT * (DIM / 4) + 255) / 256;
    const int eb          = (NEDGES + 255) / 256;
    dim3 gg(NOUT / BN, NROWS_PAD / BM);   // (12, 391)

    // ---- Prep ----
    cudaMemsetAsync(cnt, 0, NNODES * sizeof(int));
    convert_x<<<rows_blocks, 256>>>((const float4*)x, A);
    convert_w2<<<w_blocks, 256>>>((const float4*)W1l, (const float4*)W1r,
                                  (const float4*)W2l, (const float4*)W2r,
                                  W1, W2);
    count_deg<<<eb, 256>>>(ei, cnt);
    blk_sum<<<NCHUNKS, 1024>>>(cnt, bsum);
    scan_bsum<<<1, 64>>>(bsum, bbase, off);
    blk_scan<<<NCHUNKS, 1024>>>(cnt, bbase, off, cur);
    fill_csr<<<eb, 256>>>(ei, cur, csr);

    // ---- Layer 1 ----
    gemm_fp16<<<gg, 256, SMEM_GEMM>>>(A, W1, T);
    agg_combine<<<NNODES / 2, 192>>>(T, off, csr, b1l, A, nullptr);

    // ---- Layer 2 ----
    gemm_fp16<<<gg, 256, SMEM_GEMM>>>(A, W2, T);
    agg_combine<<<NNODES / 2, 192>>>(T, off, csr, b2l, nullptr, out);
}